// round 2
// baseline (speedup 1.0000x reference)
#include <cuda_runtime.h>
#include <math.h>

// ---------------- problem constants ----------------
#define BB      8
#define SEQ     1124
#define ED      1024
#define NH      16
#define HD      64
#define NQ      100
#define NP      1024
#define MLPD    4096
#define MROWS   (BB*SEQ)          // 8992
#define ATT_SCALE 0.125f          // 64^-0.5
#define NEG_INF_V (-1.0e9f)

// ---------------- scratch (device globals; no allocation allowed) ----------------
__device__ float g_xn [MROWS*ED];        // LN output (reused for LN1 and LN2)
__device__ float g_qkv[MROWS*3*ED];      // qkv projection
__device__ float g_att[MROWS*ED];        // attention output (b,s,h,d) flattened
__device__ float g_x1 [MROWS*ED];        // x + attn proj (residual 1)
__device__ float g_hh [MROWS*MLPD];      // mlp hidden

// =======================================================================
// LayerNorm: one block per row, 256 threads, 1024 cols. Two-pass (matches
// reference: mean, then mean((x-m)^2)).
// =======================================================================
__global__ __launch_bounds__(256) void ln_kernel(
    const float* __restrict__ x, const float* __restrict__ g,
    const float* __restrict__ b, float* __restrict__ y)
{
    int row = blockIdx.x;
    int tid = threadIdx.x;
    const float4* xr = reinterpret_cast<const float4*>(x + (size_t)row * ED);
    float4 v = xr[tid];

    __shared__ float red[8];
    int warp = tid >> 5, lane = tid & 31;

    // ---- mean ----
    float s = v.x + v.y + v.z + v.w;
    #pragma unroll
    for (int o = 16; o > 0; o >>= 1) s += __shfl_xor_sync(0xffffffffu, s, o);
    if (lane == 0) red[warp] = s;
    __syncthreads();
    if (warp == 0) {
        float t = (lane < 8) ? red[lane] : 0.0f;
        #pragma unroll
        for (int o = 4; o > 0; o >>= 1) t += __shfl_xor_sync(0xffffffffu, t, o);
        if (lane == 0) red[0] = t;
    }
    __syncthreads();
    float mean = red[0] * (1.0f / ED);
    __syncthreads();  // everyone has read red[0] before it is reused

    // ---- variance ----
    float dx = v.x - mean, dy = v.y - mean, dz = v.z - mean, dw = v.w - mean;
    float sq = dx*dx + dy*dy + dz*dz + dw*dw;
    #pragma unroll
    for (int o = 16; o > 0; o >>= 1) sq += __shfl_xor_sync(0xffffffffu, sq, o);
    if (lane == 0) red[warp] = sq;
    __syncthreads();
    if (warp == 0) {
        float t = (lane < 8) ? red[lane] : 0.0f;
        #pragma unroll
        for (int o = 4; o > 0; o >>= 1) t += __shfl_xor_sync(0xffffffffu, t, o);
        if (lane == 0) red[0] = t;
    }
    __syncthreads();
    float rstd = rsqrtf(red[0] * (1.0f / ED) + 1e-6f);

    float4 gv = reinterpret_cast<const float4*>(g)[tid];
    float4 bv = reinterpret_cast<const float4*>(b)[tid];
    float4 o4;
    o4.x = dx * rstd * gv.x + bv.x;
    o4.y = dy * rstd * gv.y + bv.y;
    o4.z = dz * rstd * gv.z + bv.z;
    o4.w = dw * rstd * gv.w + bv.w;
    reinterpret_cast<float4*>(y + (size_t)row * ED)[tid] = o4;
}

// =======================================================================
// SIMT fp32 GEMM: C[M,N] = A[M,K] @ B[K,N] (+ epilogue)
// 128x128 block tile, BK=8, 256 threads, 8x8 per-thread micro-tile,
// double-buffered smem. N, K multiples of 8/128 as used; M guarded.
// =======================================================================
#define EPI_NONE      0
#define EPI_BIAS_RES  1
#define EPI_BIAS_GELU 2

template<int EPI>
__global__ __launch_bounds__(256) void gemm_kernel(
    const float* __restrict__ A, const float* __restrict__ Bw,
    const float* __restrict__ bias, const float* __restrict__ resid,
    float* __restrict__ C, int M, int N, int K)
{
    __shared__ float As[2][8][128];
    __shared__ float Bs[2][8][128];

    int tid  = threadIdx.x;
    int row0 = blockIdx.y * 128;
    int col0 = blockIdx.x * 128;

    // A tile loader: 128 rows x 8 cols, one float4 per thread
    int arow = tid >> 1;          // 0..127
    int acol = (tid & 1) * 4;     // 0 or 4
    int ar   = row0 + arow; if (ar > M - 1) ar = M - 1;   // clamp (stores guarded)
    const float* Aptr = A + (size_t)ar * K + acol;

    // B tile loader: 8 rows x 128 cols, one float4 per thread
    int brow = tid >> 5;          // 0..7
    int bcol = (tid & 31) * 4;    // 0..124
    const float* Bptr = Bw + (size_t)brow * N + col0 + bcol;

    int ty = tid >> 4, tx = tid & 15;

    float acc[8][8];
    #pragma unroll
    for (int i = 0; i < 8; i++)
        #pragma unroll
        for (int j = 0; j < 8; j++) acc[i][j] = 0.0f;

    // prologue: tile 0
    {
        float4 a  = *reinterpret_cast<const float4*>(Aptr);
        float4 bb = *reinterpret_cast<const float4*>(Bptr);
        As[0][acol + 0][arow] = a.x;
        As[0][acol + 1][arow] = a.y;
        As[0][acol + 2][arow] = a.z;
        As[0][acol + 3][arow] = a.w;
        *reinterpret_cast<float4*>(&Bs[0][brow][bcol]) = bb;
    }
    __syncthreads();

    int nT = K >> 3;
    for (int t = 0; t < nT; t++) {
        float4 a  = make_float4(0.f, 0.f, 0.f, 0.f);
        float4 bb = make_float4(0.f, 0.f, 0.f, 0.f);
        if (t + 1 < nT) {
            a  = *reinterpret_cast<const float4*>(Aptr + (size_t)(t + 1) * 8);
            bb = *reinterpret_cast<const float4*>(Bptr + (size_t)(t + 1) * 8 * N);
        }
        int cur = t & 1;
        #pragma unroll
        for (int k = 0; k < 8; k++) {
            float4 a0 = *reinterpret_cast<const float4*>(&As[cur][k][ty * 8]);
            float4 a1 = *reinterpret_cast<const float4*>(&As[cur][k][ty * 8 + 4]);
            float4 b0 = *reinterpret_cast<const float4*>(&Bs[cur][k][tx * 8]);
            float4 b1 = *reinterpret_cast<const float4*>(&Bs[cur][k][tx * 8 + 4]);
            float av[8] = {a0.x, a0.y, a0.z, a0.w, a1.x, a1.y, a1.z, a1.w};
            float bv[8] = {b0.x, b0.y, b0.z, b0.w, b1.x, b1.y, b1.z, b1.w};
            #pragma unroll
            for (int i = 0; i < 8; i++)
                #pragma unroll
                for (int j = 0; j < 8; j++)
                    acc[i][j] += av[i] * bv[j];
        }
        __syncthreads();
        if (t + 1 < nT) {
            int nxt = cur ^ 1;
            As[nxt][acol + 0][arow] = a.x;
            As[nxt][acol + 1][arow] = a.y;
            As[nxt][acol + 2][arow] = a.z;
            As[nxt][acol + 3][arow] = a.w;
            *reinterpret_cast<float4*>(&Bs[nxt][brow][bcol]) = bb;
        }
        __syncthreads();
    }

    // epilogue
    #pragma unroll
    for (int i = 0; i < 8; i++) {
        int row = row0 + ty * 8 + i;
        if (row < M) {
            int col = col0 + tx * 8;
            float* cp = C + (size_t)row * N + col;
            #pragma unroll
            for (int j = 0; j < 8; j++) {
                float v = acc[i][j];
                if (EPI != EPI_NONE) v += bias[col + j];
                if (EPI == EPI_BIAS_GELU)
                    v = 0.5f * v * (1.0f + erff(v * 0.70710678118654752f));
                if (EPI == EPI_BIAS_RES)
                    v += resid[(size_t)row * N + col + j];
                cp[j] = v;
            }
        }
    }
}

// =======================================================================
// Flash attention (fp32). Block: one (qtile=64 queries, head, batch).
// 256 threads as 16x16; each thread owns a 4(q) x 4 micro-tile.
// Online softmax kept fully in registers (replicated over tx lanes via
// shfl_xor row reductions). K-chunk = 64 keys.
// Static smem, exactly 48KB:
//   Qs[64][64] | KP[64][64] (K^T d-major, later aliased as P) | Vs[64][64]
// KP holds K^T only until S=QK^T is computed; a barrier then retires it and
// the same buffer holds P (softmax probs) for the P@V product.
// =======================================================================
__global__ __launch_bounds__(256) void attn_kernel(
    const float* __restrict__ qkv, const float* __restrict__ mask,
    float* __restrict__ out)
{
    __shared__ float Qs[64 * 64];   // Qs[q*64 + d]
    __shared__ float KP[64 * 64];   // phase 1: KP[d*64 + key]; phase 2: P[q*64 + key]
    __shared__ float Vs[64 * 64];   // Vs[key*64 + d]

    int qt = blockIdx.x;      // 0..17
    int h  = blockIdx.y;      // 0..15
    int b  = blockIdx.z;      // 0..7
    int tid = threadIdx.x;
    int ty = tid >> 4, tx = tid & 15;
    int r0 = ty * 4, c0 = tx * 4;
    int q0 = qt * 64;
    size_t baserow = (size_t)b * SEQ;

    // ---- load Q tile ----
    {
        int r  = tid >> 2;
        int d0 = (tid & 3) * 16;
        int qg = q0 + r;
        float4* dst = reinterpret_cast<float4*>(Qs + r * 64 + d0);
        if (qg < SEQ) {
            const float4* src = reinterpret_cast<const float4*>(
                qkv + (baserow + qg) * 3072 + h * 64 + d0);
            dst[0] = src[0]; dst[1] = src[1]; dst[2] = src[2]; dst[3] = src[3];
        } else {
            float4 z = make_float4(0.f, 0.f, 0.f, 0.f);
            dst[0] = z; dst[1] = z; dst[2] = z; dst[3] = z;
        }
    }

    float o[4][4];
    float m[4], l[4];
    #pragma unroll
    for (int i = 0; i < 4; i++) {
        m[i] = -3.0e38f; l[i] = 0.0f;
        #pragma unroll
        for (int j = 0; j < 4; j++) o[i][j] = 0.0f;
    }

    const int nKC = (SEQ + 63) / 64;   // 18
    for (int kc = 0; kc < nKC; kc++) {
        __syncthreads();   // prev chunk's P/V reads done (also covers Q load on kc=0)

        // ---- load K (d-major, into KP) and V chunk ----
        {
            int key = tid >> 2;
            int d0  = (tid & 3) * 16;
            int kg  = kc * 64 + key;
            if (kg < SEQ) {
                const float4* ks = reinterpret_cast<const float4*>(
                    qkv + (baserow + kg) * 3072 + 1024 + h * 64 + d0);
                #pragma unroll
                for (int u = 0; u < 4; u++) {
                    float4 vv = ks[u];
                    int d = d0 + u * 4;
                    KP[(d + 0) * 64 + key] = vv.x;
                    KP[(d + 1) * 64 + key] = vv.y;
                    KP[(d + 2) * 64 + key] = vv.z;
                    KP[(d + 3) * 64 + key] = vv.w;
                }
                const float4* vsrc = reinterpret_cast<const float4*>(
                    qkv + (baserow + kg) * 3072 + 2048 + h * 64 + d0);
                float4* vdst = reinterpret_cast<float4*>(Vs + key * 64 + d0);
                #pragma unroll
                for (int u = 0; u < 4; u++) vdst[u] = vsrc[u];
            } else {
                #pragma unroll
                for (int u = 0; u < 4; u++) {
                    int d = d0 + u * 4;
                    KP[(d + 0) * 64 + key] = 0.f;
                    KP[(d + 1) * 64 + key] = 0.f;
                    KP[(d + 2) * 64 + key] = 0.f;
                    KP[(d + 3) * 64 + key] = 0.f;
                }
                float4 z = make_float4(0.f, 0.f, 0.f, 0.f);
                float4* vdst = reinterpret_cast<float4*>(Vs + key * 64 + d0);
                #pragma unroll
                for (int u = 0; u < 4; u++) vdst[u] = z;
            }
        }
        __syncthreads();

        // ---- S = Q K^T (4x4 per thread) ----
        float s[4][4];
        #pragma unroll
        for (int i = 0; i < 4; i++)
            #pragma unroll
            for (int j = 0; j < 4; j++) s[i][j] = 0.0f;

        #pragma unroll 2
        for (int kk = 0; kk < 64; kk += 4) {
            float qbuf[4][4];
            #pragma unroll
            for (int i = 0; i < 4; i++) {
                float4 q4 = *reinterpret_cast<const float4*>(Qs + (r0 + i) * 64 + kk);
                qbuf[i][0] = q4.x; qbuf[i][1] = q4.y; qbuf[i][2] = q4.z; qbuf[i][3] = q4.w;
            }
            #pragma unroll
            for (int u = 0; u < 4; u++) {
                float4 k4 = *reinterpret_cast<const float4*>(KP + (kk + u) * 64 + c0);
                #pragma unroll
                for (int i = 0; i < 4; i++) {
                    float qa = qbuf[i][u];
                    s[i][0] += qa * k4.x;
                    s[i][1] += qa * k4.y;
                    s[i][2] += qa * k4.z;
                    s[i][3] += qa * k4.w;
                }
            }
        }

        // ---- scale + mask (registers only) ----
        #pragma unroll
        for (int i = 0; i < 4; i++) {
            int qg = q0 + r0 + i;
            #pragma unroll
            for (int j = 0; j < 4; j++) {
                int kg = kc * 64 + c0 + j;
                float sv = s[i][j] * ATT_SCALE;
                if (kg >= SEQ) {
                    sv = -1.0e30f;
                } else if (qg >= NP && qg < SEQ && kg < NP) {
                    float mv = mask[((size_t)(b * NQ + (qg - NP))) * NP + kg];
                    if (!(mv > 0.5f)) sv = NEG_INF_V;
                }
                s[i][j] = sv;
            }
        }

        __syncthreads();   // all K^T reads done; KP buffer may now hold P

        // ---- online softmax (row reductions over tx lanes via shfl) ----
        #pragma unroll
        for (int i = 0; i < 4; i++) {
            float rm = fmaxf(fmaxf(s[i][0], s[i][1]), fmaxf(s[i][2], s[i][3]));
            rm = fmaxf(rm, __shfl_xor_sync(0xffffffffu, rm, 1));
            rm = fmaxf(rm, __shfl_xor_sync(0xffffffffu, rm, 2));
            rm = fmaxf(rm, __shfl_xor_sync(0xffffffffu, rm, 4));
            rm = fmaxf(rm, __shfl_xor_sync(0xffffffffu, rm, 8));
            float nm = fmaxf(m[i], rm);
            float alpha = __expf(m[i] - nm);
            float p0 = __expf(s[i][0] - nm);
            float p1 = __expf(s[i][1] - nm);
            float p2 = __expf(s[i][2] - nm);
            float p3 = __expf(s[i][3] - nm);
            float rs = p0 + p1 + p2 + p3;
            rs += __shfl_xor_sync(0xffffffffu, rs, 1);
            rs += __shfl_xor_sync(0xffffffffu, rs, 2);
            rs += __shfl_xor_sync(0xffffffffu, rs, 4);
            rs += __shfl_xor_sync(0xffffffffu, rs, 8);
            m[i] = nm;
            l[i] = l[i] * alpha + rs;
            float* pr = KP + (r0 + i) * 64 + c0;   // P lives in KP now
            pr[0] = p0; pr[1] = p1; pr[2] = p2; pr[3] = p3;
            o[i][0] *= alpha; o[i][1] *= alpha; o[i][2] *= alpha; o[i][3] *= alpha;
        }
        __syncthreads();

        // ---- O += P @ V ----
        #pragma unroll 2
        for (int kk = 0; kk < 64; kk += 4) {
            float pbuf[4][4];
            #pragma unroll
            for (int i = 0; i < 4; i++) {
                float4 p4 = *reinterpret_cast<const float4*>(KP + (r0 + i) * 64 + kk);
                pbuf[i][0] = p4.x; pbuf[i][1] = p4.y; pbuf[i][2] = p4.z; pbuf[i][3] = p4.w;
            }
            #pragma unroll
            for (int u = 0; u < 4; u++) {
                float4 v4 = *reinterpret_cast<const float4*>(Vs + (kk + u) * 64 + c0);
                #pragma unroll
                for (int i = 0; i < 4; i++) {
                    float pa = pbuf[i][u];
                    o[i][0] += pa * v4.x;
                    o[i][1] += pa * v4.y;
                    o[i][2] += pa * v4.z;
                    o[i][3] += pa * v4.w;
                }
            }
        }
    }

    // ---- write O / l ----
    #pragma unroll
    for (int i = 0; i < 4; i++) {
        int qg = q0 + r0 + i;
        if (qg < SEQ) {
            float inv = 1.0f / l[i];
            float4 ov = make_float4(o[i][0] * inv, o[i][1] * inv,
                                    o[i][2] * inv, o[i][3] * inv);
            *reinterpret_cast<float4*>(out + (baserow + qg) * 1024 + h * 64 + c0) = ov;
        }
    }
}

// =======================================================================
// launch
// =======================================================================
extern "C" void kernel_launch(void* const* d_in, const int* in_sizes, int n_in,
                              void* d_out, int out_size)
{
    const float* x      = (const float*)d_in[0];
    const float* mask   = (const float*)d_in[1];
    const float* qkv_w  = (const float*)d_in[2];
    const float* proj_w = (const float*)d_in[3];
    const float* proj_b = (const float*)d_in[4];
    const float* ln1_g  = (const float*)d_in[5];
    const float* ln1_b  = (const float*)d_in[6];
    const float* ln2_g  = (const float*)d_in[7];
    const float* ln2_b  = (const float*)d_in[8];
    const float* fc1_w  = (const float*)d_in[9];
    const float* fc1_b  = (const float*)d_in[10];
    const float* fc2_w  = (const float*)d_in[11];
    const float* fc2_b  = (const float*)d_in[12];
    float* out = (float*)d_out;

    void* p;
    cudaGetSymbolAddress(&p, g_xn);  float* xn   = (float*)p;
    cudaGetSymbolAddress(&p, g_qkv); float* qkvb = (float*)p;
    cudaGetSymbolAddress(&p, g_att); float* att  = (float*)p;
    cudaGetSymbolAddress(&p, g_x1);  float* x1   = (float*)p;
    cudaGetSymbolAddress(&p, g_hh);  float* hh   = (float*)p;

    dim3 blk(256);
    int mtiles = (MROWS + 127) / 128;   // 71

    // 1) LN1
    ln_kernel<<<MROWS, blk>>>(x, ln1_g, ln1_b, xn);

    // 2) QKV GEMM: [8992,1024] @ [1024,3072]
    gemm_kernel<EPI_NONE><<<dim3(3072 / 128, mtiles), blk>>>(
        xn, qkv_w, nullptr, nullptr, qkvb, MROWS, 3072, 1024);

    // 3) attention (static 48KB smem)
    attn_kernel<<<dim3((SEQ + 63) / 64, NH, BB), blk>>>(qkvb, mask, att);

    // 4) proj + bias + residual(x)
    gemm_kernel<EPI_BIAS_RES><<<dim3(1024 / 128, mtiles), blk>>>(
        att, proj_w, proj_b, x, x1, MROWS, 1024, 1024);

    // 5) LN2
    ln_kernel<<<MROWS, blk>>>(x1, ln2_g, ln2_b, xn);

    // 6) fc1 + bias + exact GELU
    gemm_kernel<EPI_BIAS_GELU><<<dim3(4096 / 128, mtiles), blk>>>(
        xn, fc1_w, fc1_b, nullptr, hh, MROWS, 4096, 1024);

    // 7) fc2 + bias + residual(x1) -> out
    gemm_kernel<EPI_BIAS_RES><<<dim3(1024 / 128, mtiles), blk>>>(
        hh, fc2_w, fc2_b, x1, out, MROWS, 1024, 4096);
}

// round 3
// speedup vs baseline: 1.1680x; 1.1680x over previous
#include <cuda_runtime.h>
#include <math.h>

// ---------------- problem constants ----------------
#define BB      8
#define SEQ     1124
#define ED      1024
#define NH      16
#define HD      64
#define NQ      100
#define NP      1024
#define MLPD    4096
#define MROWS   (BB*SEQ)          // 8992
#define ATT_SCALE 0.125f
#define NEG_INF_V (-1.0e9f)

// ---------------- scratch ----------------
__device__ float g_xn [MROWS*ED];
__device__ float g_qkv[MROWS*3*ED];
__device__ float g_att[MROWS*ED];
__device__ float g_x1 [MROWS*ED];
__device__ float g_hh [MROWS*MLPD];

// =======================================================================
// LayerNorm (unchanged from R2)
// =======================================================================
__global__ __launch_bounds__(256) void ln_kernel(
    const float* __restrict__ x, const float* __restrict__ g,
    const float* __restrict__ b, float* __restrict__ y)
{
    int row = blockIdx.x;
    int tid = threadIdx.x;
    const float4* xr = reinterpret_cast<const float4*>(x + (size_t)row * ED);
    float4 v = xr[tid];

    __shared__ float red[8];
    int warp = tid >> 5, lane = tid & 31;

    float s = v.x + v.y + v.z + v.w;
    #pragma unroll
    for (int o = 16; o > 0; o >>= 1) s += __shfl_xor_sync(0xffffffffu, s, o);
    if (lane == 0) red[warp] = s;
    __syncthreads();
    if (warp == 0) {
        float t = (lane < 8) ? red[lane] : 0.0f;
        #pragma unroll
        for (int o = 4; o > 0; o >>= 1) t += __shfl_xor_sync(0xffffffffu, t, o);
        if (lane == 0) red[0] = t;
    }
    __syncthreads();
    float mean = red[0] * (1.0f / ED);
    __syncthreads();

    float dx = v.x - mean, dy = v.y - mean, dz = v.z - mean, dw = v.w - mean;
    float sq = dx*dx + dy*dy + dz*dz + dw*dw;
    #pragma unroll
    for (int o = 16; o > 0; o >>= 1) sq += __shfl_xor_sync(0xffffffffu, sq, o);
    if (lane == 0) red[warp] = sq;
    __syncthreads();
    if (warp == 0) {
        float t = (lane < 8) ? red[lane] : 0.0f;
        #pragma unroll
        for (int o = 4; o > 0; o >>= 1) t += __shfl_xor_sync(0xffffffffu, t, o);
        if (lane == 0) red[0] = t;
    }
    __syncthreads();
    float rstd = rsqrtf(red[0] * (1.0f / ED) + 1e-6f);

    float4 gv = reinterpret_cast<const float4*>(g)[tid];
    float4 bv = reinterpret_cast<const float4*>(b)[tid];
    float4 o4;
    o4.x = dx * rstd * gv.x + bv.x;
    o4.y = dy * rstd * gv.y + bv.y;
    o4.z = dz * rstd * gv.z + bv.z;
    o4.w = dw * rstd * gv.w + bv.w;
    reinterpret_cast<float4*>(y + (size_t)row * ED)[tid] = o4;
}

// =======================================================================
// Tensor-core GEMM: C[M,N] = A[M,K] @ B[K,N] (+ epilogue)
// mma.sync.m16n8k8.tf32 with 3xTF32 compensation (fp32-level accuracy).
// 128x128 block, BK=16, 256 threads = 8 warps (2x4), warp tile 64x32.
// smem: A transposed [16][132] (pad -> conflict-free fragment LDS), B [16][132].
// =======================================================================
#define EPI_NONE      0
#define EPI_BIAS_RES  1
#define EPI_BIAS_GELU 2

__device__ __forceinline__ void tf32_split(float v, unsigned& hi, unsigned& lo) {
    asm("cvt.rna.tf32.f32 %0, %1;" : "=r"(hi) : "f"(v));
    float r = v - __uint_as_float(hi);
    asm("cvt.rna.tf32.f32 %0, %1;" : "=r"(lo) : "f"(r));
}

__device__ __forceinline__ void mma_tf32(float* c,
    unsigned a0, unsigned a1, unsigned a2, unsigned a3,
    unsigned b0, unsigned b1)
{
    asm volatile(
        "mma.sync.aligned.m16n8k8.row.col.f32.tf32.tf32.f32 "
        "{%0,%1,%2,%3}, {%4,%5,%6,%7}, {%8,%9}, {%0,%1,%2,%3};"
        : "+f"(c[0]), "+f"(c[1]), "+f"(c[2]), "+f"(c[3])
        : "r"(a0), "r"(a1), "r"(a2), "r"(a3), "r"(b0), "r"(b1));
}

template<int EPI>
__global__ __launch_bounds__(256) void gemm_tc(
    const float* __restrict__ A, const float* __restrict__ Bw,
    const float* __restrict__ bias, const float* __restrict__ resid,
    float* __restrict__ C, int M, int N, int K)
{
    __shared__ float As[2][16][132];   // [k][m], padded
    __shared__ float Bs[2][16][132];   // [k][n], padded

    int tid  = threadIdx.x;
    int lane = tid & 31;
    int wid  = tid >> 5;
    int wm   = wid & 1;       // 0..1 -> 64 rows each
    int wn   = wid >> 1;      // 0..3 -> 32 cols each
    int lr   = lane >> 2;     // 0..7
    int lc   = lane & 3;      // 0..3

    int row0 = blockIdx.y * 128;
    int col0 = blockIdx.x * 128;

    // loaders
    int arow = tid >> 1;            // 0..127
    int acol = (tid & 1) * 8;       // 0 or 8
    int ar = row0 + arow; if (ar > M - 1) ar = M - 1;
    const float* Aptr = A + (size_t)ar * K + acol;

    int brow = tid >> 4;            // 0..15
    int bcol = (tid & 15) * 8;      // 0..120
    const float* Bptr = Bw + (size_t)brow * N + col0 + bcol;

    float acc[4][4][4];
    #pragma unroll
    for (int i = 0; i < 4; i++)
        #pragma unroll
        for (int j = 0; j < 4; j++)
            #pragma unroll
            for (int r = 0; r < 4; r++) acc[i][j][r] = 0.0f;

    // prologue: tile 0
    {
        float4 a0 = *reinterpret_cast<const float4*>(Aptr);
        float4 a1 = *reinterpret_cast<const float4*>(Aptr + 4);
        float4 b0 = *reinterpret_cast<const float4*>(Bptr);
        float4 b1 = *reinterpret_cast<const float4*>(Bptr + 4);
        As[0][acol+0][arow] = a0.x; As[0][acol+1][arow] = a0.y;
        As[0][acol+2][arow] = a0.z; As[0][acol+3][arow] = a0.w;
        As[0][acol+4][arow] = a1.x; As[0][acol+5][arow] = a1.y;
        As[0][acol+6][arow] = a1.z; As[0][acol+7][arow] = a1.w;
        *reinterpret_cast<float4*>(&Bs[0][brow][bcol])     = b0;
        *reinterpret_cast<float4*>(&Bs[0][brow][bcol + 4]) = b1;
    }
    __syncthreads();

    int nT = K >> 4;
    for (int t = 0; t < nT; t++) {
        float4 pa0, pa1, pb0, pb1;
        if (t + 1 < nT) {
            const float* ap = Aptr + (size_t)(t + 1) * 16;
            const float* bp = Bptr + (size_t)(t + 1) * 16 * N;
            pa0 = *reinterpret_cast<const float4*>(ap);
            pa1 = *reinterpret_cast<const float4*>(ap + 4);
            pb0 = *reinterpret_cast<const float4*>(bp);
            pb1 = *reinterpret_cast<const float4*>(bp + 4);
        }
        int cur = t & 1;

        #pragma unroll
        for (int ks = 0; ks < 2; ks++) {
            int k0 = ks * 8;
            // ---- A fragments (4 m-tiles), split hi/lo ----
            unsigned ahi[4][4], alo[4][4];
            #pragma unroll
            for (int mt = 0; mt < 4; mt++) {
                int m0 = wm * 64 + mt * 16 + lr;
                float a0 = As[cur][k0 + lc    ][m0];
                float a1 = As[cur][k0 + lc    ][m0 + 8];
                float a2 = As[cur][k0 + 4 + lc][m0];
                float a3 = As[cur][k0 + 4 + lc][m0 + 8];
                tf32_split(a0, ahi[mt][0], alo[mt][0]);
                tf32_split(a1, ahi[mt][1], alo[mt][1]);
                tf32_split(a2, ahi[mt][2], alo[mt][2]);
                tf32_split(a3, ahi[mt][3], alo[mt][3]);
            }
            // ---- B fragments (4 n-tiles), split hi/lo ----
            unsigned bhi[4][2], blo[4][2];
            #pragma unroll
            for (int nt = 0; nt < 4; nt++) {
                int n0 = wn * 32 + nt * 8 + lr;
                float b0 = Bs[cur][k0 + lc    ][n0];
                float b1 = Bs[cur][k0 + 4 + lc][n0];
                tf32_split(b0, bhi[nt][0], blo[nt][0]);
                tf32_split(b1, bhi[nt][1], blo[nt][1]);
            }
            // ---- 3xTF32 MMAs ----
            #pragma unroll
            for (int mt = 0; mt < 4; mt++)
                #pragma unroll
                for (int nt = 0; nt < 4; nt++) {
                    mma_tf32(acc[mt][nt], ahi[mt][0], ahi[mt][1], ahi[mt][2], ahi[mt][3],
                             bhi[nt][0], bhi[nt][1]);
                    mma_tf32(acc[mt][nt], ahi[mt][0], ahi[mt][1], ahi[mt][2], ahi[mt][3],
                             blo[nt][0], blo[nt][1]);
                    mma_tf32(acc[mt][nt], alo[mt][0], alo[mt][1], alo[mt][2], alo[mt][3],
                             bhi[nt][0], bhi[nt][1]);
                }
        }

        __syncthreads();
        if (t + 1 < nT) {
            int nxt = cur ^ 1;
            As[nxt][acol+0][arow] = pa0.x; As[nxt][acol+1][arow] = pa0.y;
            As[nxt][acol+2][arow] = pa0.z; As[nxt][acol+3][arow] = pa0.w;
            As[nxt][acol+4][arow] = pa1.x; As[nxt][acol+5][arow] = pa1.y;
            As[nxt][acol+6][arow] = pa1.z; As[nxt][acol+7][arow] = pa1.w;
            *reinterpret_cast<float4*>(&Bs[nxt][brow][bcol])     = pb0;
            *reinterpret_cast<float4*>(&Bs[nxt][brow][bcol + 4]) = pb1;
        }
        __syncthreads();
    }

    // ---- epilogue ----
    #pragma unroll
    for (int mt = 0; mt < 4; mt++) {
        int r1 = row0 + wm * 64 + mt * 16 + lr;
        int r2 = r1 + 8;
        #pragma unroll
        for (int nt = 0; nt < 4; nt++) {
            int col = col0 + wn * 32 + nt * 8 + 2 * lc;
            float bsum0 = 0.f, bsum1 = 0.f;
            if (EPI != EPI_NONE) { bsum0 = bias[col]; bsum1 = bias[col + 1]; }
            #pragma unroll
            for (int half = 0; half < 2; half++) {
                int row = half ? r2 : r1;
                if (row < M) {
                    float v0 = acc[mt][nt][half * 2 + 0] + bsum0;
                    float v1 = acc[mt][nt][half * 2 + 1] + bsum1;
                    if (EPI == EPI_BIAS_GELU) {
                        v0 = 0.5f * v0 * (1.0f + erff(v0 * 0.70710678118654752f));
                        v1 = 0.5f * v1 * (1.0f + erff(v1 * 0.70710678118654752f));
                    }
                    if (EPI == EPI_BIAS_RES) {
                        const float2 rr = *reinterpret_cast<const float2*>(
                            resid + (size_t)row * N + col);
                        v0 += rr.x; v1 += rr.y;
                    }
                    *reinterpret_cast<float2*>(C + (size_t)row * N + col) =
                        make_float2(v0, v1);
                }
            }
        }
    }
}

// =======================================================================
// Flash attention (unchanged from R2, static 48KB smem)
// =======================================================================
__global__ __launch_bounds__(256) void attn_kernel(
    const float* __restrict__ qkv, const float* __restrict__ mask,
    float* __restrict__ out)
{
    __shared__ float Qs[64 * 64];
    __shared__ float KP[64 * 64];
    __shared__ float Vs[64 * 64];

    int qt = blockIdx.x;
    int h  = blockIdx.y;
    int b  = blockIdx.z;
    int tid = threadIdx.x;
    int ty = tid >> 4, tx = tid & 15;
    int r0 = ty * 4, c0 = tx * 4;
    int q0 = qt * 64;
    size_t baserow = (size_t)b * SEQ;

    {
        int r  = tid >> 2;
        int d0 = (tid & 3) * 16;
        int qg = q0 + r;
        float4* dst = reinterpret_cast<float4*>(Qs + r * 64 + d0);
        if (qg < SEQ) {
            const float4* src = reinterpret_cast<const float4*>(
                qkv + (baserow + qg) * 3072 + h * 64 + d0);
            dst[0] = src[0]; dst[1] = src[1]; dst[2] = src[2]; dst[3] = src[3];
        } else {
            float4 z = make_float4(0.f, 0.f, 0.f, 0.f);
            dst[0] = z; dst[1] = z; dst[2] = z; dst[3] = z;
        }
    }

    float o[4][4];
    float m[4], l[4];
    #pragma unroll
    for (int i = 0; i < 4; i++) {
        m[i] = -3.0e38f; l[i] = 0.0f;
        #pragma unroll
        for (int j = 0; j < 4; j++) o[i][j] = 0.0f;
    }

    const int nKC = (SEQ + 63) / 64;
    for (int kc = 0; kc < nKC; kc++) {
        __syncthreads();

        {
            int key = tid >> 2;
            int d0  = (tid & 3) * 16;
            int kg  = kc * 64 + key;
            if (kg < SEQ) {
                const float4* ks = reinterpret_cast<const float4*>(
                    qkv + (baserow + kg) * 3072 + 1024 + h * 64 + d0);
                #pragma unroll
                for (int u = 0; u < 4; u++) {
                    float4 vv = ks[u];
                    int d = d0 + u * 4;
                    KP[(d + 0) * 64 + key] = vv.x;
                    KP[(d + 1) * 64 + key] = vv.y;
                    KP[(d + 2) * 64 + key] = vv.z;
                    KP[(d + 3) * 64 + key] = vv.w;
                }
                const float4* vsrc = reinterpret_cast<const float4*>(
                    qkv + (baserow + kg) * 3072 + 2048 + h * 64 + d0);
                float4* vdst = reinterpret_cast<float4*>(Vs + key * 64 + d0);
                #pragma unroll
                for (int u = 0; u < 4; u++) vdst[u] = vsrc[u];
            } else {
                #pragma unroll
                for (int u = 0; u < 4; u++) {
                    int d = d0 + u * 4;
                    KP[(d + 0) * 64 + key] = 0.f;
                    KP[(d + 1) * 64 + key] = 0.f;
                    KP[(d + 2) * 64 + key] = 0.f;
                    KP[(d + 3) * 64 + key] = 0.f;
                }
                float4 z = make_float4(0.f, 0.f, 0.f, 0.f);
                float4* vdst = reinterpret_cast<float4*>(Vs + key * 64 + d0);
                #pragma unroll
                for (int u = 0; u < 4; u++) vdst[u] = z;
            }
        }
        __syncthreads();

        float s[4][4];
        #pragma unroll
        for (int i = 0; i < 4; i++)
            #pragma unroll
            for (int j = 0; j < 4; j++) s[i][j] = 0.0f;

        #pragma unroll 2
        for (int kk = 0; kk < 64; kk += 4) {
            float qbuf[4][4];
            #pragma unroll
            for (int i = 0; i < 4; i++) {
                float4 q4 = *reinterpret_cast<const float4*>(Qs + (r0 + i) * 64 + kk);
                qbuf[i][0] = q4.x; qbuf[i][1] = q4.y; qbuf[i][2] = q4.z; qbuf[i][3] = q4.w;
            }
            #pragma unroll
            for (int u = 0; u < 4; u++) {
                float4 k4 = *reinterpret_cast<const float4*>(KP + (kk + u) * 64 + c0);
                #pragma unroll
                for (int i = 0; i < 4; i++) {
                    float qa = qbuf[i][u];
                    s[i][0] += qa * k4.x;
                    s[i][1] += qa * k4.y;
                    s[i][2] += qa * k4.z;
                    s[i][3] += qa * k4.w;
                }
            }
        }

        #pragma unroll
        for (int i = 0; i < 4; i++) {
            int qg = q0 + r0 + i;
            #pragma unroll
            for (int j = 0; j < 4; j++) {
                int kg = kc * 64 + c0 + j;
                float sv = s[i][j] * ATT_SCALE;
                if (kg >= SEQ) {
                    sv = -1.0e30f;
                } else if (qg >= NP && qg < SEQ && kg < NP) {
                    float mv = mask[((size_t)(b * NQ + (qg - NP))) * NP + kg];
                    if (!(mv > 0.5f)) sv = NEG_INF_V;
                }
                s[i][j] = sv;
            }
        }

        __syncthreads();

        #pragma unroll
        for (int i = 0; i < 4; i++) {
            float rm = fmaxf(fmaxf(s[i][0], s[i][1]), fmaxf(s[i][2], s[i][3]));
            rm = fmaxf(rm, __shfl_xor_sync(0xffffffffu, rm, 1));
            rm = fmaxf(rm, __shfl_xor_sync(0xffffffffu, rm, 2));
            rm = fmaxf(rm, __shfl_xor_sync(0xffffffffu, rm, 4));
            rm = fmaxf(rm, __shfl_xor_sync(0xffffffffu, rm, 8));
            float nm = fmaxf(m[i], rm);
            float alpha = __expf(m[i] - nm);
            float p0 = __expf(s[i][0] - nm);
            float p1 = __expf(s[i][1] - nm);
            float p2 = __expf(s[i][2] - nm);
            float p3 = __expf(s[i][3] - nm);
            float rs = p0 + p1 + p2 + p3;
            rs += __shfl_xor_sync(0xffffffffu, rs, 1);
            rs += __shfl_xor_sync(0xffffffffu, rs, 2);
            rs += __shfl_xor_sync(0xffffffffu, rs, 4);
            rs += __shfl_xor_sync(0xffffffffu, rs, 8);
            m[i] = nm;
            l[i] = l[i] * alpha + rs;
            float* pr = KP + (r0 + i) * 64 + c0;
            pr[0] = p0; pr[1] = p1; pr[2] = p2; pr[3] = p3;
            o[i][0] *= alpha; o[i][1] *= alpha; o[i][2] *= alpha; o[i][3] *= alpha;
        }
        __syncthreads();

        #pragma unroll 2
        for (int kk = 0; kk < 64; kk += 4) {
            float pbuf[4][4];
            #pragma unroll
            for (int i = 0; i < 4; i++) {
                float4 p4 = *reinterpret_cast<const float4*>(KP + (r0 + i) * 64 + kk);
                pbuf[i][0] = p4.x; pbuf[i][1] = p4.y; pbuf[i][2] = p4.z; pbuf[i][3] = p4.w;
            }
            #pragma unroll
            for (int u = 0; u < 4; u++) {
                float4 v4 = *reinterpret_cast<const float4*>(Vs + (kk + u) * 64 + c0);
                #pragma unroll
                for (int i = 0; i < 4; i++) {
                    float pa = pbuf[i][u];
                    o[i][0] += pa * v4.x;
                    o[i][1] += pa * v4.y;
                    o[i][2] += pa * v4.z;
                    o[i][3] += pa * v4.w;
                }
            }
        }
    }

    #pragma unroll
    for (int i = 0; i < 4; i++) {
        int qg = q0 + r0 + i;
        if (qg < SEQ) {
            float inv = 1.0f / l[i];
            float4 ov = make_float4(o[i][0] * inv, o[i][1] * inv,
                                    o[i][2] * inv, o[i][3] * inv);
            *reinterpret_cast<float4*>(out + (baserow + qg) * 1024 + h * 64 + c0) = ov;
        }
    }
}

// =======================================================================
// launch
// =======================================================================
extern "C" void kernel_launch(void* const* d_in, const int* in_sizes, int n_in,
                              void* d_out, int out_size)
{
    const float* x      = (const float*)d_in[0];
    const float* mask   = (const float*)d_in[1];
    const float* qkv_w  = (const float*)d_in[2];
    const float* proj_w = (const float*)d_in[3];
    const float* proj_b = (const float*)d_in[4];
    const float* ln1_g  = (const float*)d_in[5];
    const float* ln1_b  = (const float*)d_in[6];
    const float* ln2_g  = (const float*)d_in[7];
    const float* ln2_b  = (const float*)d_in[8];
    const float* fc1_w  = (const float*)d_in[9];
    const float* fc1_b  = (const float*)d_in[10];
    const float* fc2_w  = (const float*)d_in[11];
    const float* fc2_b  = (const float*)d_in[12];
    float* out = (float*)d_out;

    void* p;
    cudaGetSymbolAddress(&p, g_xn);  float* xn   = (float*)p;
    cudaGetSymbolAddress(&p, g_qkv); float* qkvb = (float*)p;
    cudaGetSymbolAddress(&p, g_att); float* att  = (float*)p;
    cudaGetSymbolAddress(&p, g_x1);  float* x1   = (float*)p;
    cudaGetSymbolAddress(&p, g_hh);  float* hh   = (float*)p;

    dim3 blk(256);
    int mtiles = (MROWS + 127) / 128;   // 71

    ln_kernel<<<MROWS, blk>>>(x, ln1_g, ln1_b, xn);

    gemm_tc<EPI_NONE><<<dim3(3072 / 128, mtiles), blk>>>(
        xn, qkv_w, nullptr, nullptr, qkvb, MROWS, 3072, 1024);

    attn_kernel<<<dim3((SEQ + 63) / 64, NH, BB), blk>>>(qkvb, mask, att);

    gemm_tc<EPI_BIAS_RES><<<dim3(1024 / 128, mtiles), blk>>>(
        att, proj_w, proj_b, x, x1, MROWS, 1024, 1024);

    ln_kernel<<<MROWS, blk>>>(x1, ln2_g, ln2_b, xn);

    gemm_tc<EPI_BIAS_GELU><<<dim3(4096 / 128, mtiles), blk>>>(
        xn, fc1_w, fc1_b, nullptr, hh, MROWS, 4096, 1024);

    gemm_tc<EPI_BIAS_RES><<<dim3(1024 / 128, mtiles), blk>>>(
        hh, fc2_w, fc2_b, x1, out, MROWS, 1024, 4096);
}

// round 5
// speedup vs baseline: 1.5101x; 1.2929x over previous
#include <cuda_runtime.h>
#include <cuda_bf16.h>
#include <math.h>

// ---------------- problem constants ----------------
#define BB      8
#define SEQ     1124
#define ED      1024
#define NH      16
#define HD      64
#define NQ      100
#define NP      1024
#define MLPD    4096
#define MROWS   (BB*SEQ)          // 8992
#define ATT_SCALE 0.125f
#define NEG_INF_V (-1.0e9f)

// ---------------- scratch ----------------
__device__ float g_xn [MROWS*ED];
__device__ float g_qkv[MROWS*3*ED];
__device__ float g_att[MROWS*ED];
__device__ float g_x1 [MROWS*ED];
__device__ float g_hh [MROWS*MLPD];

// =======================================================================
// LayerNorm
// =======================================================================
__global__ __launch_bounds__(256) void ln_kernel(
    const float* __restrict__ x, const float* __restrict__ g,
    const float* __restrict__ b, float* __restrict__ y)
{
    int row = blockIdx.x;
    int tid = threadIdx.x;
    const float4* xr = reinterpret_cast<const float4*>(x + (size_t)row * ED);
    float4 v = xr[tid];

    __shared__ float red[8];
    int warp = tid >> 5, lane = tid & 31;

    float s = v.x + v.y + v.z + v.w;
    #pragma unroll
    for (int o = 16; o > 0; o >>= 1) s += __shfl_xor_sync(0xffffffffu, s, o);
    if (lane == 0) red[warp] = s;
    __syncthreads();
    if (warp == 0) {
        float t = (lane < 8) ? red[lane] : 0.0f;
        #pragma unroll
        for (int o = 4; o > 0; o >>= 1) t += __shfl_xor_sync(0xffffffffu, t, o);
        if (lane == 0) red[0] = t;
    }
    __syncthreads();
    float mean = red[0] * (1.0f / ED);
    __syncthreads();

    float dx = v.x - mean, dy = v.y - mean, dz = v.z - mean, dw = v.w - mean;
    float sq = dx*dx + dy*dy + dz*dz + dw*dw;
    #pragma unroll
    for (int o = 16; o > 0; o >>= 1) sq += __shfl_xor_sync(0xffffffffu, sq, o);
    if (lane == 0) red[warp] = sq;
    __syncthreads();
    if (warp == 0) {
        float t = (lane < 8) ? red[lane] : 0.0f;
        #pragma unroll
        for (int o = 4; o > 0; o >>= 1) t += __shfl_xor_sync(0xffffffffu, t, o);
        if (lane == 0) red[0] = t;
    }
    __syncthreads();
    float rstd = rsqrtf(red[0] * (1.0f / ED) + 1e-6f);

    float4 gv = reinterpret_cast<const float4*>(g)[tid];
    float4 bv = reinterpret_cast<const float4*>(b)[tid];
    float4 o4;
    o4.x = dx * rstd * gv.x + bv.x;
    o4.y = dy * rstd * gv.y + bv.y;
    o4.z = dz * rstd * gv.z + bv.z;
    o4.w = dw * rstd * gv.w + bv.w;
    reinterpret_cast<float4*>(y + (size_t)row * ED)[tid] = o4;
}

// =======================================================================
// bf16 split-precision tensor-core GEMM: C = A@B (+ epilogue)
// mma.sync.m16n8k16.bf16, 3 MMAs: hi*hi + hi*lo + lo*hi.
// hi = fp32 truncated to top 16 bits (zero-cost split via byte_perm);
// lo = rn-bf16 of the residual. Split done once, in the smem loader.
// smem: packed k-pairs (u32 = 2 bf16), [kpair][m or n], stride 132.
// 128x128 block, BK=16, 256 threads = 8 warps (2x4), warp tile 64x32.
// =======================================================================
#define EPI_NONE      0
#define EPI_BIAS_RES  1
#define EPI_BIAS_GELU 2

__device__ __forceinline__ void split_pair(float v0, float v1,
                                           unsigned& hi, unsigned& lo)
{
    unsigned b0 = __float_as_uint(v0), b1 = __float_as_uint(v1);
    hi = __byte_perm(b0, b1, 0x7632);                  // {top16(v0) lo, top16(v1) hi}
    float l0 = v0 - __uint_as_float(b0 & 0xffff0000u);
    float l1 = v1 - __uint_as_float(b1 & 0xffff0000u);
    __nv_bfloat162 t = __floats2bfloat162_rn(l0, l1);  // .x=l0 (low half)
    lo = *reinterpret_cast<unsigned*>(&t);
}

__device__ __forceinline__ void mma_bf16(float* c, const unsigned* a,
                                         const unsigned* b)
{
    asm volatile(
        "mma.sync.aligned.m16n8k16.row.col.f32.bf16.bf16.f32 "
        "{%0,%1,%2,%3}, {%4,%5,%6,%7}, {%8,%9}, {%0,%1,%2,%3};"
        : "+f"(c[0]), "+f"(c[1]), "+f"(c[2]), "+f"(c[3])
        : "r"(a[0]), "r"(a[1]), "r"(a[2]), "r"(a[3]), "r"(b[0]), "r"(b[1]));
}

template<int EPI>
__global__ __launch_bounds__(256) void gemm_tc(
    const float* __restrict__ A, const float* __restrict__ Bw,
    const float* __restrict__ bias, const float* __restrict__ resid,
    float* __restrict__ C, int M, int N, int K)
{
    __shared__ unsigned Ah[2][8][132], Al[2][8][132];
    __shared__ unsigned Bh[2][8][132], Bl[2][8][132];

    int tid  = threadIdx.x;
    int lane = tid & 31;
    int wid  = tid >> 5;
    int wm   = wid & 1;
    int wn   = wid >> 1;
    int lr   = lane >> 2;
    int lc   = lane & 3;

    int row0 = blockIdx.y * 128;
    int col0 = blockIdx.x * 128;

    int arow  = tid >> 1;
    int acolp = (tid & 1) * 4;
    int ar = row0 + arow; if (ar > M - 1) ar = M - 1;
    const float* Aptr = A + (size_t)ar * K + acolp * 2;

    int kr = tid >> 5;
    int n0 = lane * 4;
    const float* Bptr = Bw + (size_t)(2 * kr) * N + col0 + n0;

    float acc[4][4][4];
    #pragma unroll
    for (int i = 0; i < 4; i++)
        #pragma unroll
        for (int j = 0; j < 4; j++)
            #pragma unroll
            for (int r = 0; r < 4; r++) acc[i][j][r] = 0.0f;

    // prologue: stage tile 0 into buf 0
    {
        float4 a0 = *reinterpret_cast<const float4*>(Aptr);
        float4 a1 = *reinterpret_cast<const float4*>(Aptr + 4);
        unsigned h, l;
        split_pair(a0.x, a0.y, h, l); Ah[0][acolp+0][arow] = h; Al[0][acolp+0][arow] = l;
        split_pair(a0.z, a0.w, h, l); Ah[0][acolp+1][arow] = h; Al[0][acolp+1][arow] = l;
        split_pair(a1.x, a1.y, h, l); Ah[0][acolp+2][arow] = h; Al[0][acolp+2][arow] = l;
        split_pair(a1.z, a1.w, h, l); Ah[0][acolp+3][arow] = h; Al[0][acolp+3][arow] = l;

        float4 r0 = *reinterpret_cast<const float4*>(Bptr);
        float4 r1 = *reinterpret_cast<const float4*>(Bptr + N);
        uint4 h4, l4;
        split_pair(r0.x, r1.x, h4.x, l4.x);
        split_pair(r0.y, r1.y, h4.y, l4.y);
        split_pair(r0.z, r1.z, h4.z, l4.z);
        split_pair(r0.w, r1.w, h4.w, l4.w);
        *reinterpret_cast<uint4*>(&Bh[0][kr][n0]) = h4;
        *reinterpret_cast<uint4*>(&Bl[0][kr][n0]) = l4;
    }
    __syncthreads();

    int nT = K >> 4;
    for (int t = 0; t < nT; t++) {
        float4 pa0, pa1, pb0, pb1;
        if (t + 1 < nT) {
            const float* ap = Aptr + (size_t)(t + 1) * 16;
            const float* bp = Bptr + (size_t)(t + 1) * 16 * N;
            pa0 = *reinterpret_cast<const float4*>(ap);
            pa1 = *reinterpret_cast<const float4*>(ap + 4);
            pb0 = *reinterpret_cast<const float4*>(bp);
            pb1 = *reinterpret_cast<const float4*>(bp + N);
        }
        int cur = t & 1;

        unsigned ah[4][4], al4[4][4];
        #pragma unroll
        for (int mt = 0; mt < 4; mt++) {
            int m0 = wm * 64 + mt * 16 + lr;
            ah[mt][0]  = Ah[cur][lc    ][m0];
            ah[mt][1]  = Ah[cur][lc    ][m0 + 8];
            ah[mt][2]  = Ah[cur][lc + 4][m0];
            ah[mt][3]  = Ah[cur][lc + 4][m0 + 8];
            al4[mt][0] = Al[cur][lc    ][m0];
            al4[mt][1] = Al[cur][lc    ][m0 + 8];
            al4[mt][2] = Al[cur][lc + 4][m0];
            al4[mt][3] = Al[cur][lc + 4][m0 + 8];
        }
        unsigned bh[4][2], bl4[4][2];
        #pragma unroll
        for (int nt = 0; nt < 4; nt++) {
            int nn = wn * 32 + nt * 8 + lr;
            bh[nt][0]  = Bh[cur][lc    ][nn];
            bh[nt][1]  = Bh[cur][lc + 4][nn];
            bl4[nt][0] = Bl[cur][lc    ][nn];
            bl4[nt][1] = Bl[cur][lc + 4][nn];
        }

        #pragma unroll
        for (int mt = 0; mt < 4; mt++)
            #pragma unroll
            for (int nt = 0; nt < 4; nt++) {
                mma_bf16(acc[mt][nt], ah[mt],  bh[nt]);
                mma_bf16(acc[mt][nt], ah[mt],  bl4[nt]);
                mma_bf16(acc[mt][nt], al4[mt], bh[nt]);
            }

        __syncthreads();
        if (t + 1 < nT) {
            int nxt = cur ^ 1;
            unsigned h, l;
            split_pair(pa0.x, pa0.y, h, l); Ah[nxt][acolp+0][arow] = h; Al[nxt][acolp+0][arow] = l;
            split_pair(pa0.z, pa0.w, h, l); Ah[nxt][acolp+1][arow] = h; Al[nxt][acolp+1][arow] = l;
            split_pair(pa1.x, pa1.y, h, l); Ah[nxt][acolp+2][arow] = h; Al[nxt][acolp+2][arow] = l;
            split_pair(pa1.z, pa1.w, h, l); Ah[nxt][acolp+3][arow] = h; Al[nxt][acolp+3][arow] = l;
            uint4 h4, l4;
            split_pair(pb0.x, pb1.x, h4.x, l4.x);
            split_pair(pb0.y, pb1.y, h4.y, l4.y);
            split_pair(pb0.z, pb1.z, h4.z, l4.z);
            split_pair(pb0.w, pb1.w, h4.w, l4.w);
            *reinterpret_cast<uint4*>(&Bh[nxt][kr][n0]) = h4;
            *reinterpret_cast<uint4*>(&Bl[nxt][kr][n0]) = l4;
        }
        __syncthreads();
    }

    // ---- epilogue ----
    #pragma unroll
    for (int mt = 0; mt < 4; mt++) {
        int r1 = row0 + wm * 64 + mt * 16 + lr;
        int r2 = r1 + 8;
        #pragma unroll
        for (int nt = 0; nt < 4; nt++) {
            int col = col0 + wn * 32 + nt * 8 + 2 * lc;
            float bsum0 = 0.f, bsum1 = 0.f;
            if (EPI != EPI_NONE) { bsum0 = bias[col]; bsum1 = bias[col + 1]; }
            #pragma unroll
            for (int half = 0; half < 2; half++) {
                int row = half ? r2 : r1;
                if (row < M) {
                    float v0 = acc[mt][nt][half * 2 + 0] + bsum0;
                    float v1 = acc[mt][nt][half * 2 + 1] + bsum1;
                    if (EPI == EPI_BIAS_GELU) {
                        v0 = 0.5f * v0 * (1.0f + erff(v0 * 0.70710678118654752f));
                        v1 = 0.5f * v1 * (1.0f + erff(v1 * 0.70710678118654752f));
                    }
                    if (EPI == EPI_BIAS_RES) {
                        const float2 rr = *reinterpret_cast<const float2*>(
                            resid + (size_t)row * N + col);
                        v0 += rr.x; v1 += rr.y;
                    }
                    *reinterpret_cast<float2*>(C + (size_t)row * N + col) =
                        make_float2(v0, v1);
                }
            }
        }
    }
}

// =======================================================================
// Flash attention (static 48KB smem)
// =======================================================================
__global__ __launch_bounds__(256) void attn_kernel(
    const float* __restrict__ qkv, const float* __restrict__ mask,
    float* __restrict__ out)
{
    __shared__ float Qs[64 * 64];
    __shared__ float KP[64 * 64];
    __shared__ float Vs[64 * 64];

    int qt = blockIdx.x;
    int h  = blockIdx.y;
    int b  = blockIdx.z;
    int tid = threadIdx.x;
    int ty = tid >> 4, tx = tid & 15;
    int r0 = ty * 4, c0 = tx * 4;
    int q0 = qt * 64;
    size_t baserow = (size_t)b * SEQ;

    {
        int r  = tid >> 2;
        int d0 = (tid & 3) * 16;
        int qg = q0 + r;
        float4* dst = reinterpret_cast<float4*>(Qs + r * 64 + d0);
        if (qg < SEQ) {
            const float4* src = reinterpret_cast<const float4*>(
                qkv + (baserow + qg) * 3072 + h * 64 + d0);
            dst[0] = src[0]; dst[1] = src[1]; dst[2] = src[2]; dst[3] = src[3];
        } else {
            float4 z = make_float4(0.f, 0.f, 0.f, 0.f);
            dst[0] = z; dst[1] = z; dst[2] = z; dst[3] = z;
        }
    }

    float o[4][4];
    float m[4], l[4];
    #pragma unroll
    for (int i = 0; i < 4; i++) {
        m[i] = -3.0e38f; l[i] = 0.0f;
        #pragma unroll
        for (int j = 0; j < 4; j++) o[i][j] = 0.0f;
    }

    const int nKC = (SEQ + 63) / 64;
    for (int kc = 0; kc < nKC; kc++) {
        __syncthreads();

        {
            int key = tid >> 2;
            int d0  = (tid & 3) * 16;
            int kg  = kc * 64 + key;
            if (kg < SEQ) {
                const float4* ks = reinterpret_cast<const float4*>(
                    qkv + (baserow + kg) * 3072 + 1024 + h * 64 + d0);
                #pragma unroll
                for (int u = 0; u < 4; u++) {
                    float4 vv = ks[u];
                    int d = d0 + u * 4;
                    KP[(d + 0) * 64 + key] = vv.x;
                    KP[(d + 1) * 64 + key] = vv.y;
                    KP[(d + 2) * 64 + key] = vv.z;
                    KP[(d + 3) * 64 + key] = vv.w;
                }
                const float4* vsrc = reinterpret_cast<const float4*>(
                    qkv + (baserow + kg) * 3072 + 2048 + h * 64 + d0);
                float4* vdst = reinterpret_cast<float4*>(Vs + key * 64 + d0);
                #pragma unroll
                for (int u = 0; u < 4; u++) vdst[u] = vsrc[u];
            } else {
                #pragma unroll
                for (int u = 0; u < 4; u++) {
                    int d = d0 + u * 4;
                    KP[(d + 0) * 64 + key] = 0.f;
                    KP[(d + 1) * 64 + key] = 0.f;
                    KP[(d + 2) * 64 + key] = 0.f;
                    KP[(d + 3) * 64 + key] = 0.f;
                }
                float4 z = make_float4(0.f, 0.f, 0.f, 0.f);
                float4* vdst = reinterpret_cast<float4*>(Vs + key * 64 + d0);
                #pragma unroll
                for (int u = 0; u < 4; u++) vdst[u] = z;
            }
        }
        __syncthreads();

        float s[4][4];
        #pragma unroll
        for (int i = 0; i < 4; i++)
            #pragma unroll
            for (int j = 0; j < 4; j++) s[i][j] = 0.0f;

        #pragma unroll 2
        for (int kk = 0; kk < 64; kk += 4) {
            float qbuf[4][4];
            #pragma unroll
            for (int i = 0; i < 4; i++) {
                float4 q4 = *reinterpret_cast<const float4*>(Qs + (r0 + i) * 64 + kk);
                qbuf[i][0] = q4.x; qbuf[i][1] = q4.y; qbuf[i][2] = q4.z; qbuf[i][3] = q4.w;
            }
            #pragma unroll
            for (int u = 0; u < 4; u++) {
                float4 k4 = *reinterpret_cast<const float4*>(KP + (kk + u) * 64 + c0);
                #pragma unroll
                for (int i = 0; i < 4; i++) {
                    float qa = qbuf[i][u];
                    s[i][0] += qa * k4.x;
                    s[i][1] += qa * k4.y;
                    s[i][2] += qa * k4.z;
                    s[i][3] += qa * k4.w;
                }
            }
        }

        #pragma unroll
        for (int i = 0; i < 4; i++) {
            int qg = q0 + r0 + i;
            #pragma unroll
            for (int j = 0; j < 4; j++) {
                int kg = kc * 64 + c0 + j;
                float sv = s[i][j] * ATT_SCALE;
                if (kg >= SEQ) {
                    sv = -1.0e30f;
                } else if (qg >= NP && qg < SEQ && kg < NP) {
                    float mv = mask[((size_t)(b * NQ + (qg - NP))) * NP + kg];
                    if (!(mv > 0.5f)) sv = NEG_INF_V;
                }
                s[i][j] = sv;
            }
        }

        __syncthreads();

        #pragma unroll
        for (int i = 0; i < 4; i++) {
            float rm = fmaxf(fmaxf(s[i][0], s[i][1]), fmaxf(s[i][2], s[i][3]));
            rm = fmaxf(rm, __shfl_xor_sync(0xffffffffu, rm, 1));
            rm = fmaxf(rm, __shfl_xor_sync(0xffffffffu, rm, 2));
            rm = fmaxf(rm, __shfl_xor_sync(0xffffffffu, rm, 4));
            rm = fmaxf(rm, __shfl_xor_sync(0xffffffffu, rm, 8));
            float nm = fmaxf(m[i], rm);
            float alpha = __expf(m[i] - nm);
            float p0 = __expf(s[i][0] - nm);
            float p1 = __expf(s[i][1] - nm);
            float p2 = __expf(s[i][2] - nm);
            float p3 = __expf(s[i][3] - nm);
            float rs = p0 + p1 + p2 + p3;
            rs += __shfl_xor_sync(0xffffffffu, rs, 1);
            rs += __shfl_xor_sync(0xffffffffu, rs, 2);
            rs += __shfl_xor_sync(0xffffffffu, rs, 4);
            rs += __shfl_xor_sync(0xffffffffu, rs, 8);
            m[i] = nm;
            l[i] = l[i] * alpha + rs;
            float* pr = KP + (r0 + i) * 64 + c0;
            pr[0] = p0; pr[1] = p1; pr[2] = p2; pr[3] = p3;
            o[i][0] *= alpha; o[i][1] *= alpha; o[i][2] *= alpha; o[i][3] *= alpha;
        }
        __syncthreads();

        #pragma unroll 2
        for (int kk = 0; kk < 64; kk += 4) {
            float pbuf[4][4];
            #pragma unroll
            for (int i = 0; i < 4; i++) {
                float4 p4 = *reinterpret_cast<const float4*>(KP + (r0 + i) * 64 + kk);
                pbuf[i][0] = p4.x; pbuf[i][1] = p4.y; pbuf[i][2] = p4.z; pbuf[i][3] = p4.w;
            }
            #pragma unroll
            for (int u = 0; u < 4; u++) {
                float4 v4 = *reinterpret_cast<const float4*>(Vs + (kk + u) * 64 + c0);
                #pragma unroll
                for (int i = 0; i < 4; i++) {
                    float pa = pbuf[i][u];
                    o[i][0] += pa * v4.x;
                    o[i][1] += pa * v4.y;
                    o[i][2] += pa * v4.z;
                    o[i][3] += pa * v4.w;
                }
            }
        }
    }

    #pragma unroll
    for (int i = 0; i < 4; i++) {
        int qg = q0 + r0 + i;
        if (qg < SEQ) {
            float inv = 1.0f / l[i];
            float4 ov = make_float4(o[i][0] * inv, o[i][1] * inv,
                                    o[i][2] * inv, o[i][3] * inv);
            *reinterpret_cast<float4*>(out + (baserow + qg) * 1024 + h * 64 + c0) = ov;
        }
    }
}

// =======================================================================
// launch
// =======================================================================
extern "C" void kernel_launch(void* const* d_in, const int* in_sizes, int n_in,
                              void* d_out, int out_size)
{
    const float* x      = (const float*)d_in[0];
    const float* mask   = (const float*)d_in[1];
    const float* qkv_w  = (const float*)d_in[2];
    const float* proj_w = (const float*)d_in[3];
    const float* proj_b = (const float*)d_in[4];
    const float* ln1_g  = (const float*)d_in[5];
    const float* ln1_b  = (const float*)d_in[6];
    const float* ln2_g  = (const float*)d_in[7];
    const float* ln2_b  = (const float*)d_in[8];
    const float* fc1_w  = (const float*)d_in[9];
    const float* fc1_b  = (const float*)d_in[10];
    const float* fc2_w  = (const float*)d_in[11];
    const float* fc2_b  = (const float*)d_in[12];
    float* out = (float*)d_out;

    void* p;
    cudaGetSymbolAddress(&p, g_xn);  float* xn   = (float*)p;
    cudaGetSymbolAddress(&p, g_qkv); float* qkvb = (float*)p;
    cudaGetSymbolAddress(&p, g_att); float* att  = (float*)p;
    cudaGetSymbolAddress(&p, g_x1);  float* x1   = (float*)p;
    cudaGetSymbolAddress(&p, g_hh);  float* hh   = (float*)p;

    dim3 blk(256);
    int mtiles = (MROWS + 127) / 128;   // 71

    ln_kernel<<<MROWS, blk>>>(x, ln1_g, ln1_b, xn);

    gemm_tc<EPI_NONE><<<dim3(3072 / 128, mtiles), blk>>>(
        xn, qkv_w, nullptr, nullptr, qkvb, MROWS, 3072, 1024);

    attn_kernel<<<dim3((SEQ + 63) / 64, NH, BB), blk>>>(qkvb, mask, att);

    gemm_tc<EPI_BIAS_RES><<<dim3(1024 / 128, mtiles), blk>>>(
        att, proj_w, proj_b, x, x1, MROWS, 1024, 1024);

    ln_kernel<<<MROWS, blk>>>(x1, ln2_g, ln2_b, xn);

    gemm_tc<EPI_BIAS_GELU><<<dim3(4096 / 128, mtiles), blk>>>(
        xn, fc1_w, fc1_b, nullptr, hh, MROWS, 4096, 1024);

    gemm_tc<EPI_BIAS_RES><<<dim3(1024 / 128, mtiles), blk>>>(
        hh, fc2_w, fc2_b, x1, out, MROWS, 1024, 4096);
}